// round 5
// baseline (speedup 1.0000x reference)
#include <cuda_runtime.h>
#include <cuda_bf16.h>
#include <cstdint>

// Problem constants
#define B_TOT 16384
#define F_TOT 32
#define D_IN  64
#define H_HID 128

#define ROWS_PER_BLK 128
#define THREADS      512
#define D2           (D_IN / 2)     // 32 k-pair steps
#define RP_STRIDE    130            // padded inner dim (rows) for rp, in 8B units
#define SMEM_ULL     (D2 * RP_STRIDE + D2 * H_HID)   // 4160 + 4096 = 8256 ULLs
#define SMEM_BYTES   (SMEM_ULL * 8)                   // 66048 bytes

// Packed fp32x2 FMA: c.lo += a.lo*b.lo ; c.hi += a.hi*b.hi (Blackwell sm_100+)
#define FMA2(c, a, b) asm("fma.rn.f32x2 %0, %1, %2, %0;" : "+l"(c) : "l"(a), "l"(b))

__global__ void __launch_bounds__(THREADS, 1)
cont_mlp_kernel(const float* __restrict__ X,
                const float* __restrict__ r_,
                const float* __restrict__ W1,
                const float* __restrict__ b1,
                const float* __restrict__ W2,
                const float* __restrict__ b2,
                float* __restrict__ out)
{
    extern __shared__ unsigned long long sm[];
    unsigned long long* rp = sm;                 // [D2][RP_STRIDE] : (r[2d2], r[2d2+1]) per row
    unsigned long long* Wp = sm + D2 * RP_STRIDE; // [D2][H]        : (W1[2d2][h], W1[2d2+1][h])

    const int f       = blockIdx.y;
    const int rowbase = blockIdx.x * ROWS_PER_BLK;
    const int t       = threadIdx.x;

    // ---- Stage W1[f] into smem, interleaving even/odd d rows into float2 pairs ----
    {
        const float* W1f = W1 + (size_t)f * D_IN * H_HID;
        float2* Wp2 = reinterpret_cast<float2*>(Wp);
        #pragma unroll
        for (int idx = t; idx < D2 * H_HID; idx += THREADS) {
            int d2 = idx >> 7;          // /128
            int h  = idx & (H_HID - 1);
            float w0 = W1f[(2 * d2)     * H_HID + h];
            float w1 = W1f[(2 * d2 + 1) * H_HID + h];
            Wp2[d2 * H_HID + h] = make_float2(w0, w1);
        }
    }

    // ---- Stage r tile: rp[d2][row] = (r[row][2d2], r[row][2d2+1]) ----
    {
        const unsigned long long* rg = reinterpret_cast<const unsigned long long*>(r_);
        #pragma unroll
        for (int idx = t; idx < ROWS_PER_BLK * D2; idx += THREADS) {
            int row = idx >> 5;          // /32
            int d2  = idx & (D2 - 1);
            // r_[(rowg*F + f)*D] as 8-byte words: 32 ULLs per (row,f)
            size_t base = ((size_t)(rowbase + row) * F_TOT + f) * D2;
            rp[d2 * RP_STRIDE + row] = rg[base + d2];
        }
    }
    __syncthreads();

    const int lane = t & 31;       // h-group: handles h = lane + 32*j
    const int w    = t >> 5;       // warp id: handles rows row0..row0+7
    const int row0 = w * 8;

    // 8 rows x 4 h-columns, each acc packed (even-d sum, odd-d sum)
    unsigned long long acc[8][4];
    #pragma unroll
    for (int m = 0; m < 8; ++m)
        #pragma unroll
        for (int j = 0; j < 4; ++j)
            acc[m][j] = 0ull;   // packed (0.0f, 0.0f)

    // ---- Main loop over 32 d-pairs ----
    #pragma unroll 4
    for (int d2 = 0; d2 < D2; ++d2) {
        // r pairs for our 8 rows (broadcast within warp; 16B-aligned vector loads)
        const ulonglong2* rrow = reinterpret_cast<const ulonglong2*>(&rp[d2 * RP_STRIDE + row0]);
        ulonglong2 ra = rrow[0];
        ulonglong2 rb = rrow[1];
        ulonglong2 rc = rrow[2];
        ulonglong2 rd = rrow[3];
        unsigned long long rr[8] = { ra.x, ra.y, rb.x, rb.y, rc.x, rc.y, rd.x, rd.y };

        // W pairs: lane-strided, conflict-free dense warp reads
        unsigned long long ww[4];
        #pragma unroll
        for (int j = 0; j < 4; ++j)
            ww[j] = Wp[d2 * H_HID + lane + 32 * j];

        #pragma unroll
        for (int m = 0; m < 8; ++m)
            #pragma unroll
            for (int j = 0; j < 4; ++j)
                FMA2(acc[m][j], rr[m], ww[j]);
    }

    // ---- Layer 2: hv = relu(lo+hi+b1); partial[m] = sum_j hv * W2 ----
    float partial[8];
    #pragma unroll
    for (int m = 0; m < 8; ++m) partial[m] = 0.0f;

    #pragma unroll
    for (int j = 0; j < 4; ++j) {
        int h = lane + 32 * j;
        float b1v = b1[f * H_HID + h];
        float w2v = W2[f * H_HID + h];
        #pragma unroll
        for (int m = 0; m < 8; ++m) {
            unsigned long long a = acc[m][j];
            float lo = __uint_as_float((unsigned)(a & 0xffffffffu));
            float hi = __uint_as_float((unsigned)(a >> 32));
            float hv = lo + hi + b1v;
            hv = fmaxf(hv, 0.0f);
            partial[m] = fmaf(hv, w2v, partial[m]);
        }
    }

    // Butterfly reduce each of the 8 row-sums across the 32 lanes
    #pragma unroll
    for (int off = 16; off > 0; off >>= 1) {
        #pragma unroll
        for (int m = 0; m < 8; ++m)
            partial[m] += __shfl_xor_sync(0xffffffffu, partial[m], off);
    }

    // Lane m (m<8) writes row row0+m
    if (lane < 8) {
        float sel = partial[0];
        #pragma unroll
        for (int m = 1; m < 8; ++m)
            sel = (lane == m) ? partial[m] : sel;

        int rowg = rowbase + row0 + lane;
        float y  = fmaxf(sel + b2[f], 0.0f);
        float xv = X[(size_t)rowg * F_TOT + f];
        reinterpret_cast<float2*>(out)[(size_t)rowg * F_TOT + f] = make_float2(xv, y);
    }
}

extern "C" void kernel_launch(void* const* d_in, const int* in_sizes, int n_in,
                              void* d_out, int out_size)
{
    const float* X  = (const float*)d_in[0];
    const float* r_ = (const float*)d_in[1];
    const float* W1 = (const float*)d_in[2];
    const float* b1 = (const float*)d_in[3];
    const float* W2 = (const float*)d_in[4];
    const float* b2 = (const float*)d_in[5];
    float* out = (float*)d_out;

    cudaFuncSetAttribute(cont_mlp_kernel,
                         cudaFuncAttributeMaxDynamicSharedMemorySize, SMEM_BYTES);

    dim3 grid(B_TOT / ROWS_PER_BLK, F_TOT);   // (128, 32)
    cont_mlp_kernel<<<grid, THREADS, SMEM_BYTES>>>(X, r_, W1, b1, W2, b2, out);
}

// round 6
// speedup vs baseline: 1.0001x; 1.0001x over previous
#include <cuda_runtime.h>
#include <cuda_bf16.h>
#include <cstdint>

// Problem constants
#define B_TOT 16384
#define F_TOT 32
#define D_IN  64
#define H_HID 128

#define ROWS_PER_BLK 128
#define THREADS      512
#define D2           (D_IN / 2)     // 32 k-pair steps
#define RP_STRIDE    130            // padded inner dim (rows) for rp, in 8B units
#define SMEM_ULL     (D2 * RP_STRIDE + D2 * H_HID)   // 4160 + 4096 = 8256 ULLs
#define SMEM_BYTES   (SMEM_ULL * 8)                   // 66048 bytes

// Packed fp32x2 FMA: c.lo += a.lo*b.lo ; c.hi += a.hi*b.hi (Blackwell sm_100+)
#define FMA2(c, a, b) asm("fma.rn.f32x2 %0, %1, %2, %0;" : "+l"(c) : "l"(a), "l"(b))

__global__ void __launch_bounds__(THREADS, 1)
cont_mlp_kernel(const float* __restrict__ X,
                const float* __restrict__ r_,
                const float* __restrict__ W1,
                const float* __restrict__ b1,
                const float* __restrict__ W2,
                const float* __restrict__ b2,
                float* __restrict__ out)
{
    extern __shared__ unsigned long long sm[];
    unsigned long long* rp = sm;                 // [D2][RP_STRIDE] : (r[2d2], r[2d2+1]) per row
    unsigned long long* Wp = sm + D2 * RP_STRIDE; // [D2][H]        : (W1[2d2][h], W1[2d2+1][h])

    const int f       = blockIdx.y;
    const int rowbase = blockIdx.x * ROWS_PER_BLK;
    const int t       = threadIdx.x;

    // ---- Stage W1[f] into smem, interleaving even/odd d rows into float2 pairs ----
    {
        const float* W1f = W1 + (size_t)f * D_IN * H_HID;
        float2* Wp2 = reinterpret_cast<float2*>(Wp);
        #pragma unroll
        for (int idx = t; idx < D2 * H_HID; idx += THREADS) {
            int d2 = idx >> 7;          // /128
            int h  = idx & (H_HID - 1);
            float w0 = W1f[(2 * d2)     * H_HID + h];
            float w1 = W1f[(2 * d2 + 1) * H_HID + h];
            Wp2[d2 * H_HID + h] = make_float2(w0, w1);
        }
    }

    // ---- Stage r tile: rp[d2][row] = (r[row][2d2], r[row][2d2+1]) ----
    {
        const unsigned long long* rg = reinterpret_cast<const unsigned long long*>(r_);
        #pragma unroll
        for (int idx = t; idx < ROWS_PER_BLK * D2; idx += THREADS) {
            int row = idx >> 5;          // /32
            int d2  = idx & (D2 - 1);
            // r_[(rowg*F + f)*D] as 8-byte words: 32 ULLs per (row,f)
            size_t base = ((size_t)(rowbase + row) * F_TOT + f) * D2;
            rp[d2 * RP_STRIDE + row] = rg[base + d2];
        }
    }
    __syncthreads();

    const int lane = t & 31;       // h-group: handles h = lane + 32*j
    const int w    = t >> 5;       // warp id: handles rows row0..row0+7
    const int row0 = w * 8;

    // 8 rows x 4 h-columns, each acc packed (even-d sum, odd-d sum)
    unsigned long long acc[8][4];
    #pragma unroll
    for (int m = 0; m < 8; ++m)
        #pragma unroll
        for (int j = 0; j < 4; ++j)
            acc[m][j] = 0ull;   // packed (0.0f, 0.0f)

    // ---- Main loop over 32 d-pairs ----
    #pragma unroll 4
    for (int d2 = 0; d2 < D2; ++d2) {
        // r pairs for our 8 rows (broadcast within warp; 16B-aligned vector loads)
        const ulonglong2* rrow = reinterpret_cast<const ulonglong2*>(&rp[d2 * RP_STRIDE + row0]);
        ulonglong2 ra = rrow[0];
        ulonglong2 rb = rrow[1];
        ulonglong2 rc = rrow[2];
        ulonglong2 rd = rrow[3];
        unsigned long long rr[8] = { ra.x, ra.y, rb.x, rb.y, rc.x, rc.y, rd.x, rd.y };

        // W pairs: lane-strided, conflict-free dense warp reads
        unsigned long long ww[4];
        #pragma unroll
        for (int j = 0; j < 4; ++j)
            ww[j] = Wp[d2 * H_HID + lane + 32 * j];

        #pragma unroll
        for (int m = 0; m < 8; ++m)
            #pragma unroll
            for (int j = 0; j < 4; ++j)
                FMA2(acc[m][j], rr[m], ww[j]);
    }

    // ---- Layer 2: hv = relu(lo+hi+b1); partial[m] = sum_j hv * W2 ----
    float partial[8];
    #pragma unroll
    for (int m = 0; m < 8; ++m) partial[m] = 0.0f;

    #pragma unroll
    for (int j = 0; j < 4; ++j) {
        int h = lane + 32 * j;
        float b1v = b1[f * H_HID + h];
        float w2v = W2[f * H_HID + h];
        #pragma unroll
        for (int m = 0; m < 8; ++m) {
            unsigned long long a = acc[m][j];
            float lo = __uint_as_float((unsigned)(a & 0xffffffffu));
            float hi = __uint_as_float((unsigned)(a >> 32));
            float hv = lo + hi + b1v;
            hv = fmaxf(hv, 0.0f);
            partial[m] = fmaf(hv, w2v, partial[m]);
        }
    }

    // Butterfly reduce each of the 8 row-sums across the 32 lanes
    #pragma unroll
    for (int off = 16; off > 0; off >>= 1) {
        #pragma unroll
        for (int m = 0; m < 8; ++m)
            partial[m] += __shfl_xor_sync(0xffffffffu, partial[m], off);
    }

    // Lane m (m<8) writes row row0+m
    if (lane < 8) {
        float sel = partial[0];
        #pragma unroll
        for (int m = 1; m < 8; ++m)
            sel = (lane == m) ? partial[m] : sel;

        int rowg = rowbase + row0 + lane;
        float y  = fmaxf(sel + b2[f], 0.0f);
        float xv = X[(size_t)rowg * F_TOT + f];
        reinterpret_cast<float2*>(out)[(size_t)rowg * F_TOT + f] = make_float2(xv, y);
    }
}

extern "C" void kernel_launch(void* const* d_in, const int* in_sizes, int n_in,
                              void* d_out, int out_size)
{
    const float* X  = (const float*)d_in[0];
    const float* r_ = (const float*)d_in[1];
    const float* W1 = (const float*)d_in[2];
    const float* b1 = (const float*)d_in[3];
    const float* W2 = (const float*)d_in[4];
    const float* b2 = (const float*)d_in[5];
    float* out = (float*)d_out;

    cudaFuncSetAttribute(cont_mlp_kernel,
                         cudaFuncAttributeMaxDynamicSharedMemorySize, SMEM_BYTES);

    dim3 grid(B_TOT / ROWS_PER_BLK, F_TOT);   // (128, 32)
    cont_mlp_kernel<<<grid, THREADS, SMEM_BYTES>>>(X, r_, W1, b1, W2, b2, out);
}